// round 2
// baseline (speedup 1.0000x reference)
#include <cuda_runtime.h>

#define BB 4
#define TT 256
#define LL 216
#define EPC 12
#define EROOT 12
#define EQUAL 16
#define KK 41
#define W_NM 0.1f
#define W_ADV 0.001f

// scratch (no cudaMalloc allowed)
__device__ float g_cs[BB][TT + 1][48];   // prefix sums, channel innermost (padded)
__device__ float g_h[BB][KK][LL];        // folded harmony coefficients, k-major

// packed f32x2 FMA (FFMA2): 2 FMAs/instr, 2x scalar FFMA throughput on sm_103a
#define FMA2(d, a, b, c) \
    asm("fma.rn.f32x2 %0, %1, %2, %3;" : "=l"(d) : "l"(a), "l"(b), "l"(c))
#define DUP2(d, x) \
    asm("mov.b64 %0, {%1, %1};" : "=l"(d) : "f"(x))

// ---------------- K0: warp-level prefix scan per (batch, channel) ----------------
__global__ void scan_kernel(const float* __restrict__ apc,
                            const float* __restrict__ aroot,
                            const float* __restrict__ aqual,
                            const float* __restrict__ iroot,
                            const float* __restrict__ iqual) {
    int ch   = blockIdx.x;    // 0..40
    int b    = blockIdx.y;    // 0..3
    int lane = threadIdx.x;   // 0..31
    int t0   = lane * 8;

    float v[8];
    #pragma unroll
    for (int i = 0; i < 8; i++) {
        int t = t0 + i;
        float x;
        if (ch < 12) {
            x = apc[(b * TT + t) * EPC + ch];
        } else if (ch < 24) {
            int j = ch - 12;
            x = aroot[(b * TT + t) * EROOT + j] - W_ADV * iroot[(b * TT + t) * EROOT + j];
        } else if (ch < 40) {
            int j = ch - 24;
            x = aqual[(b * TT + t) * EQUAL + j] - W_ADV * iqual[(b * TT + t) * EQUAL + j];
        } else {
            x = 1.0f;  // channel 40 carries the -W_NM*Hs term (segment mean == 1)
        }
        v[i] = x;
    }
    #pragma unroll
    for (int i = 1; i < 8; i++) v[i] += v[i - 1];

    float s = v[7];
    #pragma unroll
    for (int off = 1; off < 32; off <<= 1) {
        float n = __shfl_up_sync(0xFFFFFFFFu, s, off);
        if (lane >= off) s += n;
    }
    float base = s - v[7];  // exclusive prefix of this lane's chunk

    #pragma unroll
    for (int i = 0; i < 8; i++) g_cs[b][t0 + i + 1][ch] = v[i] + base;
    if (lane == 0) g_cs[b][0][ch] = 0.0f;
}

// ---------------- K1: fold l-dependent scalars into h[b][k][l] ----------------
__global__ void hprep_kernel(const float* __restrict__ hpc,
                             const float* __restrict__ hroot,
                             const float* __restrict__ hqual,
                             const int* __restrict__ pc_only) {
    int b = blockIdx.x;
    int l = threadIdx.x;
    if (l >= LL) return;
    int po = pc_only ? pc_only[0] : 0;

    float hv[12];
    float hs = 0.0f;
    #pragma unroll
    for (int j = 0; j < 12; j++) {
        hv[j] = hpc[(b * LL + l) * EPC + j];
        hs += hv[j];
    }
    float coef = (1.0f + 2.0f * W_NM) - W_ADV / hs;
    #pragma unroll
    for (int j = 0; j < 12; j++) g_h[b][j][l] = hv[j] * coef - W_NM;
    #pragma unroll
    for (int j = 0; j < 12; j++) g_h[b][12 + j][l] = po ? 0.0f : hroot[(b * LL + l) * EROOT + j];
    #pragma unroll
    for (int j = 0; j < 16; j++) g_h[b][24 + j][l] = po ? 0.0f : hqual[(b * LL + l) * EQUAL + j];
    g_h[b][40][l] = -W_NM * hs;
}

// ---------------- main: tiled 41-K GEMM, FFMA2 inner loop, diagonal skip ----------------
// tile = 128 segment pairs (8 s x 16 e) x 108 l; 288 threads = 16(ts) x 18(tl)
// microtile 8(se) x 6(l), accumulators packed f32x2 along the se dimension
#define TS 8
#define TE 16
#define TL 108
#define NTHR 288

union U64F2 { unsigned long long u; float f[2]; };
union F4U { float4 f; unsigned long long u[2]; };

__global__ __launch_bounds__(NTHR, 2)
void main_kernel(float* __restrict__ out) {
    __shared__ float ms[KK][128];   // segment-mean tile, k-major
    __shared__ float hsm[KK][TL];   // harmony tile, k-major

    const int b  = blockIdx.z;
    const int lt = blockIdx.x;              // 0..1
    const int st = blockIdx.y >> 4;         // 0..31
    const int et = blockIdx.y & 15;         // 0..15
    const int s0 = st * TS, e0 = et * TE, l0 = lt * TL;
    const int tid = threadIdx.x;

    const bool tile_valid = (e0 + TE - 1) >= s0;

    const int tl = tid % 18;
    const int ts = tid / 18;

    U64F2 acc[4][6];
    #pragma unroll
    for (int i = 0; i < 4; i++)
        #pragma unroll
        for (int j = 0; j < 6; j++) acc[i][j].u = 0ull;

    if (tile_valid) {
        // fill segment tile: m = (cs[e+1] - cs[s]) / max(len,1)
        for (int idx = tid; idx < KK * 128; idx += NTHR) {
            int k = idx >> 7;
            int r = idx & 127;
            int ls = r >> 4, le = r & 15;
            int len = (e0 + le) - (s0 + ls) + 1;
            float inv = __fdividef(1.0f, (float)max(len, 1));
            ms[k][r] = (g_cs[b][e0 + le + 1][k] - g_cs[b][s0 + ls][k]) * inv;
        }
        // fill harmony tile
        for (int idx = tid; idx < KK * TL; idx += NTHR) {
            int k = idx / TL;
            int c = idx - k * TL;
            hsm[k][c] = g_h[b][k][l0 + c];
        }
        __syncthreads();

        #pragma unroll 1
        for (int k = 0; k < KK; k++) {
            F4U m0, m1;
            m0.f = *(const float4*)&ms[k][ts * 8];
            m1.f = *(const float4*)&ms[k][ts * 8 + 4];
            unsigned long long mv[4] = {m0.u[0], m0.u[1], m1.u[0], m1.u[1]};

            float2 p0 = *(const float2*)&hsm[k][tl * 2];
            float2 p1 = *(const float2*)&hsm[k][tl * 2 + 36];
            float2 p2 = *(const float2*)&hsm[k][tl * 2 + 72];
            unsigned long long hv[6];
            DUP2(hv[0], p0.x); DUP2(hv[1], p0.y);
            DUP2(hv[2], p1.x); DUP2(hv[3], p1.y);
            DUP2(hv[4], p2.x); DUP2(hv[5], p2.y);

            #pragma unroll
            for (int j = 0; j < 6; j++)
                #pragma unroll
                for (int i2 = 0; i2 < 4; i2++)
                    FMA2(acc[i2][j].u, mv[i2], hv[j], acc[i2][j].u);
        }
    }

    // store (mask e < s to zero; poisoned output must be fully written)
    #pragma unroll
    for (int i = 0; i < 8; i++) {
        int r = ts * 8 + i;
        int s = s0 + (r >> 4);
        int e = e0 + (r & 15);
        bool valid = (e >= s);
        float* po = out + ((size_t)((b * TT + s) * TT + e)) * LL + l0 + tl * 2;
        #pragma unroll
        for (int jc = 0; jc < 3; jc++) {
            float2 v;
            v.x = valid ? acc[i >> 1][2 * jc].f[i & 1]     : 0.0f;
            v.y = valid ? acc[i >> 1][2 * jc + 1].f[i & 1] : 0.0f;
            *(float2*)(po + 36 * jc) = v;
        }
    }
}

extern "C" void kernel_launch(void* const* d_in, const int* in_sizes, int n_in,
                              void* d_out, int out_size) {
    const float* apc   = (const float*)d_in[0];
    const float* aroot = (const float*)d_in[1];
    const float* aqual = (const float*)d_in[2];
    // d_in[3] = inactive_pc: unused by the reference
    const float* iroot = (const float*)d_in[4];
    const float* iqual = (const float*)d_in[5];
    const float* hpc   = (const float*)d_in[6];
    const float* hroot = (const float*)d_in[7];
    const float* hqual = (const float*)d_in[8];
    const int*   pco   = (n_in > 9) ? (const int*)d_in[9] : nullptr;

    scan_kernel<<<dim3(KK, BB), 32>>>(apc, aroot, aqual, iroot, iqual);
    hprep_kernel<<<BB, 256>>>(hpc, hroot, hqual, pco);
    main_kernel<<<dim3(2, 512, BB), NTHR>>>((float*)d_out);
}

// round 4
// speedup vs baseline: 1.1435x; 1.1435x over previous
#include <cuda_runtime.h>
#include <cstdint>

#define BB 4
#define TT 256
#define LL 216
#define EPC 12
#define EROOT 12
#define EQUAL 16
#define KK 41
#define W_NM 0.1f
#define W_ADV 0.001f

// device scratch (no cudaMalloc allowed)
__device__ float g_cs[BB][TT + 1][48];                 // prefix sums, channel-innermost
__device__ float g_h[BB][KK][LL];                      // folded harmony coefficients, k-major
__device__ __align__(16) float g_Dhi[BB][TT + 1][LL];  // D = cs @ h, fp64->fp32 hi
__device__ __align__(16) float g_Dlo[BB][TT + 1][LL];  // fp32 lo residual

// ---------------- K0: prefix scans (blocks 0..163) + h fold (blocks 164..167) ----------------
__global__ void prep_kernel(const float* __restrict__ apc,
                            const float* __restrict__ aroot,
                            const float* __restrict__ aqual,
                            const float* __restrict__ iroot,
                            const float* __restrict__ iqual,
                            const float* __restrict__ hpc,
                            const float* __restrict__ hroot,
                            const float* __restrict__ hqual,
                            const int* __restrict__ pc_only) {
    __shared__ float buf[TT];
    int bx = blockIdx.x;
    if (bx < KK * BB) {
        int ch = bx % KK;
        int b  = bx / KK;
        int t  = threadIdx.x;
        float x;
        if (ch < 12) {
            x = apc[(b * TT + t) * EPC + ch];
        } else if (ch < 24) {
            int j = ch - 12;
            x = aroot[(b * TT + t) * EROOT + j] - W_ADV * iroot[(b * TT + t) * EROOT + j];
        } else if (ch < 40) {
            int j = ch - 24;
            x = aqual[(b * TT + t) * EQUAL + j] - W_ADV * iqual[(b * TT + t) * EQUAL + j];
        } else {
            x = 1.0f;  // channel 40 carries the -W_NM*Hs term (segment mean == 1)
        }
        buf[t] = x;
        __syncthreads();
        #pragma unroll
        for (int off = 1; off < TT; off <<= 1) {
            float v = (t >= off) ? buf[t - off] : 0.0f;
            __syncthreads();
            buf[t] += v;
            __syncthreads();
        }
        g_cs[b][t + 1][ch] = buf[t];
        if (t == 0) g_cs[b][0][ch] = 0.0f;
    } else {
        int b = bx - KK * BB;
        int l = threadIdx.x;
        if (l >= LL) return;
        int po = pc_only ? pc_only[0] : 0;
        float hv[12];
        float hs = 0.0f;
        #pragma unroll
        for (int j = 0; j < 12; j++) { hv[j] = hpc[(b * LL + l) * EPC + j]; hs += hv[j]; }
        float coef = (1.0f + 2.0f * W_NM) - W_ADV / hs;
        #pragma unroll
        for (int j = 0; j < 12; j++) g_h[b][j][l] = hv[j] * coef - W_NM;
        #pragma unroll
        for (int j = 0; j < 12; j++) g_h[b][12 + j][l] = po ? 0.0f : hroot[(b * LL + l) * EROOT + j];
        #pragma unroll
        for (int j = 0; j < 16; j++) g_h[b][24 + j][l] = po ? 0.0f : hqual[(b * LL + l) * EQUAL + j];
        g_h[b][40][l] = -W_NM * hs;
    }
}

// ---------------- K1: D[b,t,l] = sum_k cs[b,t,k]*h[b,k,l] in fp64, hi/lo fp32 split ----------------
__global__ void d_kernel() {
    __shared__ float cs_s[KK];
    int t = blockIdx.x;   // 0..256
    int b = blockIdx.y;
    int l = threadIdx.x;
    if (l < KK) cs_s[l] = g_cs[b][t][l];
    __syncthreads();
    if (l >= LL) return;
    double a0 = 0.0, a1 = 0.0;
    #pragma unroll
    for (int k = 0; k < 40; k += 2) {
        a0 = fma((double)cs_s[k],     (double)g_h[b][k][l],     a0);
        a1 = fma((double)cs_s[k + 1], (double)g_h[b][k + 1][l], a1);
    }
    a0 = fma((double)cs_s[40], (double)g_h[b][40][l], a0);
    double d = a0 + a1;
    float hi = (float)d;
    g_Dhi[b][t][l] = hi;
    g_Dlo[b][t][l] = (float)(d - (double)hi);
}

// ---------------- main: out[b,s,e,l] = (D[e+1,l]-D[s,l]) * inv_len, store-bound ----------------
// tile = 8 s x 32 e x full L; 256 threads; thread: chunk c=tid&63 (c<54 active), e-group g=tid>>6
// smem floats: hiS[8*216] | loS[8*216] | hiE[32*216] | loE[32*216] | inv[256]
#define SM_LOS 1728
#define SM_HIE 3456
#define SM_LOE 10368
#define SM_INV 17280
#define SM_FLOATS 17536   // 70144 bytes

__global__ __launch_bounds__(256)
void main_kernel(float* __restrict__ out) {
    extern __shared__ float sm[];
    const int tid = threadIdx.x;
    const int et = blockIdx.x, st = blockIdx.y, b = blockIdx.z;
    const int s0 = st * 8, e0 = et * 32;

    const float* __restrict__ Dhi = &g_Dhi[b][0][0];
    const float* __restrict__ Dlo = &g_Dlo[b][0][0];

    // stage 40 D-rows (8 s-rows, 32 e-rows at t=e+1) as hi/lo
    for (int idx = tid; idx < 40 * 54; idx += 256) {
        int row = idx / 54, c = idx - row * 54;
        int t = (row < 8) ? (s0 + row) : (e0 + (row - 8) + 1);
        float4 vh = *(const float4*)(Dhi + t * LL + c * 4);
        float4 vl = *(const float4*)(Dlo + t * LL + c * 4);
        int dh = (row < 8) ? (row * LL) : (SM_HIE + (row - 8) * LL);
        int dl = dh + ((row < 8) ? SM_LOS : (SM_LOE - SM_HIE));
        *(float4*)(sm + dh + c * 4) = vh;
        *(float4*)(sm + dl + c * 4) = vl;
    }
    // inv table with validity baked in (inv = 0 for e < s)
    {
        int s = tid >> 5, e = tid & 31;
        int len = (e0 + e) - (s0 + s) + 1;
        sm[SM_INV + tid] = (len >= 1) ? __fdividef(1.0f, (float)len) : 0.0f;
    }
    __syncthreads();

    const int c = tid & 63;
    const int g = tid >> 6;
    if (c >= 54) return;

    const float4* __restrict__ hiS4 = (const float4*)sm;
    const float4* __restrict__ loS4 = (const float4*)(sm + SM_LOS);
    const float4* __restrict__ hiE4 = (const float4*)(sm + SM_HIE);
    const float4* __restrict__ loE4 = (const float4*)(sm + SM_LOE);
    const float*  __restrict__ invt = sm + SM_INV;

    float* base = out + ((size_t)(b * 65536 + s0 * 256 + e0 + g * 8)) * LL + c * 4;

    #pragma unroll 1
    for (int s = 0; s < 8; s++) {
        float4 hs = hiS4[s * 54 + c];
        float4 ls = loS4[s * 54 + c];
        float* ps = base + (size_t)s * (256 * LL);
        #pragma unroll
        for (int eg = 0; eg < 8; eg++) {
            int e = g * 8 + eg;
            float inv = invt[s * 32 + e];
            float4 he = hiE4[e * 54 + c];
            float4 le = loE4[e * 54 + c];
            float4 v;
            v.x = ((he.x - hs.x) + (le.x - ls.x)) * inv;
            v.y = ((he.y - hs.y) + (le.y - ls.y)) * inv;
            v.z = ((he.z - hs.z) + (le.z - ls.z)) * inv;
            v.w = ((he.w - hs.w) + (le.w - ls.w)) * inv;
            *(float4*)(ps + eg * LL) = v;
        }
    }
}

extern "C" void kernel_launch(void* const* d_in, const int* in_sizes, int n_in,
                              void* d_out, int out_size) {
    const float* apc   = (const float*)d_in[0];
    const float* aroot = (const float*)d_in[1];
    const float* aqual = (const float*)d_in[2];
    // d_in[3] = inactive_pc: unused by the reference
    const float* iroot = (const float*)d_in[4];
    const float* iqual = (const float*)d_in[5];
    const float* hpc   = (const float*)d_in[6];
    const float* hroot = (const float*)d_in[7];
    const float* hqual = (const float*)d_in[8];
    const int*   pco   = (n_in > 9) ? (const int*)d_in[9] : nullptr;

    static bool attr_done = false;
    if (!attr_done) {
        cudaFuncSetAttribute(main_kernel, cudaFuncAttributeMaxDynamicSharedMemorySize,
                             SM_FLOATS * 4);
        attr_done = true;
    }

    prep_kernel<<<KK * BB + BB, 256>>>(apc, aroot, aqual, iroot, iqual,
                                       hpc, hroot, hqual, pco);
    d_kernel<<<dim3(TT + 1, BB), 224>>>();
    main_kernel<<<dim3(8, 32, BB), 256, SM_FLOATS * 4>>>((float*)d_out);
}

// round 5
// speedup vs baseline: 2.1939x; 1.9185x over previous
#include <cuda_runtime.h>
#include <cstdint>

#define BB 4
#define TT 256
#define LL 216
#define EPC 12
#define EROOT 12
#define EQUAL 16
#define KK 41
#define W_NM 0.1f
#define W_ADV 0.001f

// device scratch (no cudaMalloc allowed)
__device__ float g_cs[BB][TT + 1][48];                 // prefix sums, channel-innermost
__device__ float g_h[BB][KK][LL];                      // folded harmony coefficients, k-major
__device__ __align__(16) float g_Dhi[BB][TT + 1][LL];  // D = cs @ h, compensated hi
__device__ __align__(16) float g_Dlo[BB][TT + 1][LL];  // compensation (lo) part

// ---------------- K0: prefix scans (blocks 0..163) + h fold (blocks 164..167) ----------------
__global__ void prep_kernel(const float* __restrict__ apc,
                            const float* __restrict__ aroot,
                            const float* __restrict__ aqual,
                            const float* __restrict__ iroot,
                            const float* __restrict__ iqual,
                            const float* __restrict__ hpc,
                            const float* __restrict__ hroot,
                            const float* __restrict__ hqual,
                            const int* __restrict__ pc_only) {
    __shared__ float buf[TT];
    int bx = blockIdx.x;
    if (bx < KK * BB) {
        int ch = bx % KK;
        int b  = bx / KK;
        int t  = threadIdx.x;
        float x;
        if (ch < 12) {
            x = apc[(b * TT + t) * EPC + ch];
        } else if (ch < 24) {
            int j = ch - 12;
            x = aroot[(b * TT + t) * EROOT + j] - W_ADV * iroot[(b * TT + t) * EROOT + j];
        } else if (ch < 40) {
            int j = ch - 24;
            x = aqual[(b * TT + t) * EQUAL + j] - W_ADV * iqual[(b * TT + t) * EQUAL + j];
        } else {
            x = 1.0f;  // channel 40 carries the -W_NM*Hs term (segment mean == 1)
        }
        buf[t] = x;
        __syncthreads();
        #pragma unroll
        for (int off = 1; off < TT; off <<= 1) {
            float v = (t >= off) ? buf[t - off] : 0.0f;
            __syncthreads();
            buf[t] += v;
            __syncthreads();
        }
        g_cs[b][t + 1][ch] = buf[t];
        if (t == 0) g_cs[b][0][ch] = 0.0f;
    } else {
        int b = bx - KK * BB;
        int l = threadIdx.x;
        if (l >= LL) return;
        int po = pc_only ? pc_only[0] : 0;
        float hv[12];
        float hs = 0.0f;
        #pragma unroll
        for (int j = 0; j < 12; j++) { hv[j] = hpc[(b * LL + l) * EPC + j]; hs += hv[j]; }
        float coef = (1.0f + 2.0f * W_NM) - W_ADV / hs;
        #pragma unroll
        for (int j = 0; j < 12; j++) g_h[b][j][l] = hv[j] * coef - W_NM;
        #pragma unroll
        for (int j = 0; j < 12; j++) g_h[b][12 + j][l] = po ? 0.0f : hroot[(b * LL + l) * EROOT + j];
        #pragma unroll
        for (int j = 0; j < 16; j++) g_h[b][24 + j][l] = po ? 0.0f : hqual[(b * LL + l) * EQUAL + j];
        g_h[b][40][l] = -W_NM * hs;
    }
}

// ---------------- K1: D = cs @ h via fp32 error-free compensated accumulation ----------------
// (TwoProd + TwoSum; hi/lo split produced directly. No fp64 — DFMA is ~0.22/cyc/SM on B300.)
__global__ void d_kernel() {
    __shared__ float cs_s[KK];
    int t = blockIdx.x;   // 0..256
    int b = blockIdx.y;
    int l = threadIdx.x;  // 0..215
    if (l < KK) cs_s[l] = g_cs[b][t][l];
    __syncthreads();
    if (l >= LL) return;

    float s = 0.0f, c = 0.0f;
    #pragma unroll
    for (int k = 0; k < KK; k++) {
        float a  = cs_s[k];
        float h  = g_h[b][k][l];
        float p  = a * h;
        float ep = fmaf(a, h, -p);       // exact product error
        // TwoSum: s + p
        float tt = s + p;
        float z  = tt - s;
        float e2 = (s - (tt - z)) + (p - z);
        s = tt;
        c += ep + e2;
    }
    g_Dhi[b][t][l] = s;
    g_Dlo[b][t][l] = c;
}

// ---------------- main: out[b,s,e,l] = (D[e+1,l]-D[s,l]) * inv_len, store-bound ----------------
// tile = 8 s x 32 e x full L; 256 threads; thread: chunk c=tid&63 (c<54 active), e-group g=tid>>6
// smem floats: hiS[8*216] | loS[8*216] | hiE[32*216] | loE[32*216] | inv[256]
#define SM_LOS 1728
#define SM_HIE 3456
#define SM_LOE 10368
#define SM_INV 17280
#define SM_FLOATS 17536   // 70144 bytes

__global__ __launch_bounds__(256)
void main_kernel(float* __restrict__ out) {
    extern __shared__ float sm[];
    const int tid = threadIdx.x;
    const int et = blockIdx.x, st = blockIdx.y, b = blockIdx.z;
    const int s0 = st * 8, e0 = et * 32;

    const float* __restrict__ Dhi = &g_Dhi[b][0][0];
    const float* __restrict__ Dlo = &g_Dlo[b][0][0];

    // stage 40 D-rows (8 s-rows, 32 e-rows at t=e+1) as hi/lo
    for (int idx = tid; idx < 40 * 54; idx += 256) {
        int row = idx / 54, c = idx - row * 54;
        int t = (row < 8) ? (s0 + row) : (e0 + (row - 8) + 1);
        float4 vh = *(const float4*)(Dhi + t * LL + c * 4);
        float4 vl = *(const float4*)(Dlo + t * LL + c * 4);
        int dh = (row < 8) ? (row * LL) : (SM_HIE + (row - 8) * LL);
        int dl = dh + ((row < 8) ? SM_LOS : (SM_LOE - SM_HIE));
        *(float4*)(sm + dh + c * 4) = vh;
        *(float4*)(sm + dl + c * 4) = vl;
    }
    // inv table with validity baked in (inv = 0 for e < s)
    {
        int s = tid >> 5, e = tid & 31;
        int len = (e0 + e) - (s0 + s) + 1;
        sm[SM_INV + tid] = (len >= 1) ? __fdividef(1.0f, (float)len) : 0.0f;
    }
    __syncthreads();

    const int c = tid & 63;
    const int g = tid >> 6;
    if (c >= 54) return;

    const float4* __restrict__ hiS4 = (const float4*)sm;
    const float4* __restrict__ loS4 = (const float4*)(sm + SM_LOS);
    const float4* __restrict__ hiE4 = (const float4*)(sm + SM_HIE);
    const float4* __restrict__ loE4 = (const float4*)(sm + SM_LOE);
    const float*  __restrict__ invt = sm + SM_INV;

    float* base = out + ((size_t)(b * 65536 + s0 * 256 + e0 + g * 8)) * LL + c * 4;

    #pragma unroll 1
    for (int s = 0; s < 8; s++) {
        float4 hs = hiS4[s * 54 + c];
        float4 ls = loS4[s * 54 + c];
        float* ps = base + (size_t)s * (256 * LL);
        #pragma unroll
        for (int eg = 0; eg < 8; eg++) {
            int e = g * 8 + eg;
            float inv = invt[s * 32 + e];
            float4 he = hiE4[e * 54 + c];
            float4 le = loE4[e * 54 + c];
            float4 v;
            v.x = ((he.x - hs.x) + (le.x - ls.x)) * inv;
            v.y = ((he.y - hs.y) + (le.y - ls.y)) * inv;
            v.z = ((he.z - hs.z) + (le.z - ls.z)) * inv;
            v.w = ((he.w - hs.w) + (le.w - ls.w)) * inv;
            *(float4*)(ps + eg * LL) = v;
        }
    }
}

extern "C" void kernel_launch(void* const* d_in, const int* in_sizes, int n_in,
                              void* d_out, int out_size) {
    const float* apc   = (const float*)d_in[0];
    const float* aroot = (const float*)d_in[1];
    const float* aqual = (const float*)d_in[2];
    // d_in[3] = inactive_pc: unused by the reference
    const float* iroot = (const float*)d_in[4];
    const float* iqual = (const float*)d_in[5];
    const float* hpc   = (const float*)d_in[6];
    const float* hroot = (const float*)d_in[7];
    const float* hqual = (const float*)d_in[8];
    const int*   pco   = (n_in > 9) ? (const int*)d_in[9] : nullptr;

    static bool attr_done = false;
    if (!attr_done) {
        cudaFuncSetAttribute(main_kernel, cudaFuncAttributeMaxDynamicSharedMemorySize,
                             SM_FLOATS * 4);
        attr_done = true;
    }

    prep_kernel<<<KK * BB + BB, 256>>>(apc, aroot, aqual, iroot, iqual,
                                       hpc, hroot, hqual, pco);
    d_kernel<<<dim3(TT + 1, BB), 224>>>();
    main_kernel<<<dim3(8, 32, BB), 256, SM_FLOATS * 4>>>((float*)d_out);
}

// round 6
// speedup vs baseline: 2.4513x; 1.1173x over previous
#include <cuda_runtime.h>
#include <cstdint>

#define BB 4
#define TT 256
#define LL 216
#define EPC 12
#define EROOT 12
#define EQUAL 16
#define KK 41
#define W_NM 0.1f
#define W_ADV 0.001f

// device scratch (no cudaMalloc allowed)
__device__ float g_cs[BB][TT + 1][48];                 // prefix sums, channel-innermost
__device__ float g_h[BB][KK][LL];                      // folded harmony coefficients, k-major
__device__ __align__(16) float g_Dhi[BB][TT + 1][LL];  // D = cs @ h, compensated hi
__device__ __align__(16) float g_Dlo[BB][TT + 1][LL];  // compensation (lo) part

// ---------------- K0: prefix scans (blocks 0..163, 2-barrier) + h fold (164..167) ----------------
__global__ void prep_kernel(const float* __restrict__ apc,
                            const float* __restrict__ aroot,
                            const float* __restrict__ aqual,
                            const float* __restrict__ iroot,
                            const float* __restrict__ iqual,
                            const float* __restrict__ hpc,
                            const float* __restrict__ hroot,
                            const float* __restrict__ hqual,
                            const int* __restrict__ pc_only) {
    __shared__ float wsum[8];
    int bx = blockIdx.x;
    if (bx < KK * BB) {
        int ch = bx % KK;
        int b  = bx / KK;
        int t  = threadIdx.x;
        int w  = t >> 5, lane = t & 31;
        float x;
        if (ch < 12) {
            x = apc[(b * TT + t) * EPC + ch];
        } else if (ch < 24) {
            int j = ch - 12;
            x = aroot[(b * TT + t) * EROOT + j] - W_ADV * iroot[(b * TT + t) * EROOT + j];
        } else if (ch < 40) {
            int j = ch - 24;
            x = aqual[(b * TT + t) * EQUAL + j] - W_ADV * iqual[(b * TT + t) * EQUAL + j];
        } else {
            x = 1.0f;  // channel 40 carries the -W_NM*Hs term (segment mean == 1)
        }
        // inclusive warp scan
        float v = x;
        #pragma unroll
        for (int off = 1; off < 32; off <<= 1) {
            float n = __shfl_up_sync(0xFFFFFFFFu, v, off);
            if (lane >= off) v += n;
        }
        if (lane == 31) wsum[w] = v;
        __syncthreads();
        if (t < 8) {
            float s = wsum[t];
            #pragma unroll
            for (int off = 1; off < 8; off <<= 1) {
                float n = __shfl_up_sync(0x000000FFu, s, off);
                if (t >= off) s += n;
            }
            wsum[t] = s;
        }
        __syncthreads();
        float base = (w > 0) ? wsum[w - 1] : 0.0f;
        g_cs[b][t + 1][ch] = v + base;
        if (t == 0) g_cs[b][0][ch] = 0.0f;
    } else {
        int b = bx - KK * BB;
        int l = threadIdx.x;
        if (l >= LL) return;
        int po = pc_only ? pc_only[0] : 0;
        float hv[12];
        float hs = 0.0f;
        #pragma unroll
        for (int j = 0; j < 12; j++) { hv[j] = hpc[(b * LL + l) * EPC + j]; hs += hv[j]; }
        float coef = (1.0f + 2.0f * W_NM) - W_ADV / hs;
        #pragma unroll
        for (int j = 0; j < 12; j++) g_h[b][j][l] = hv[j] * coef - W_NM;
        #pragma unroll
        for (int j = 0; j < 12; j++) g_h[b][12 + j][l] = po ? 0.0f : hroot[(b * LL + l) * EROOT + j];
        #pragma unroll
        for (int j = 0; j < 16; j++) g_h[b][24 + j][l] = po ? 0.0f : hqual[(b * LL + l) * EQUAL + j];
        g_h[b][40][l] = -W_NM * hs;
    }
}

// ---------------- K1: D = cs @ h via fp32 error-free compensated accumulation ----------------
__global__ void d_kernel() {
    __shared__ float cs_s[KK];
    int t = blockIdx.x;   // 0..256
    int b = blockIdx.y;
    int l = threadIdx.x;  // 0..215
    if (l < KK) cs_s[l] = g_cs[b][t][l];
    __syncthreads();
    if (l >= LL) return;

    float s = 0.0f, c = 0.0f;
    #pragma unroll
    for (int k = 0; k < KK; k++) {
        float a  = cs_s[k];
        float h  = g_h[b][k][l];
        float p  = a * h;
        float ep = fmaf(a, h, -p);       // exact product error
        float tt = s + p;                // TwoSum
        float z  = tt - s;
        float e2 = (s - (tt - z)) + (p - z);
        s = tt;
        c += ep + e2;
    }
    g_Dhi[b][t][l] = s;
    g_Dlo[b][t][l] = c;
}

// ---------------- main: out[b,s,e,l] = (D[e+1,l]-D[s,l]) * inv_len, store-bound ----------------
// tile = 8 s x 32 e x full L; 256 threads; thread: chunk c=tid&63 (c<54 active), e-group g=tid>>6
// grid: x = st (32) fastest so consecutive CTAs share the 32 staged E-rows in L2
// smem floats: hiS[8*216] | loS[8*216] | hiE[32*216] | loE[32*216] | inv[256]
#define SM_LOS 1728
#define SM_HIE 3456
#define SM_LOE 10368
#define SM_INV 17280
#define SM_FLOATS 17536   // 70144 bytes

__global__ __launch_bounds__(256, 2)
void main_kernel(float* __restrict__ out) {
    extern __shared__ float sm[];
    const int tid = threadIdx.x;
    const int st = blockIdx.x, et = blockIdx.y, b = blockIdx.z;
    const int s0 = st * 8, e0 = et * 32;

    const float* __restrict__ Dhi = &g_Dhi[b][0][0];
    const float* __restrict__ Dlo = &g_Dlo[b][0][0];

    // stage 40 D-rows (8 s-rows, 32 e-rows at t=e+1) as hi/lo
    for (int idx = tid; idx < 40 * 54; idx += 256) {
        int row = idx / 54, c = idx - row * 54;
        int t = (row < 8) ? (s0 + row) : (e0 + (row - 8) + 1);
        float4 vh = *(const float4*)(Dhi + t * LL + c * 4);
        float4 vl = *(const float4*)(Dlo + t * LL + c * 4);
        int dh = (row < 8) ? (row * LL) : (SM_HIE + (row - 8) * LL);
        int dl = dh + ((row < 8) ? SM_LOS : (SM_LOE - SM_HIE));
        *(float4*)(sm + dh + c * 4) = vh;
        *(float4*)(sm + dl + c * 4) = vl;
    }
    // inv table with validity baked in (inv = 0 for e < s)
    {
        int s = tid >> 5, e = tid & 31;
        int len = (e0 + e) - (s0 + s) + 1;
        sm[SM_INV + tid] = (len >= 1) ? __fdividef(1.0f, (float)len) : 0.0f;
    }
    __syncthreads();

    const int c = tid & 63;
    const int g = tid >> 6;
    if (c >= 54) return;

    const float4* __restrict__ hiS4 = (const float4*)sm;
    const float4* __restrict__ loS4 = (const float4*)(sm + SM_LOS);
    const float4* __restrict__ hiE4 = (const float4*)(sm + SM_HIE);
    const float4* __restrict__ loE4 = (const float4*)(sm + SM_LOE);
    const float*  __restrict__ invt = sm + SM_INV;

    float* base = out + ((size_t)(b * 65536 + s0 * 256 + e0 + g * 8)) * LL + c * 4;

    #pragma unroll 1
    for (int s = 0; s < 8; s++) {
        float4 hs = hiS4[s * 54 + c];
        float4 ls = loS4[s * 54 + c];
        float* ps = base + (size_t)s * (256 * LL);
        #pragma unroll
        for (int eg = 0; eg < 8; eg++) {
            int e = g * 8 + eg;
            float inv = invt[s * 32 + e];
            float4 he = hiE4[e * 54 + c];
            float4 le = loE4[e * 54 + c];
            float4 v;
            v.x = ((he.x - hs.x) + (le.x - ls.x)) * inv;
            v.y = ((he.y - hs.y) + (le.y - ls.y)) * inv;
            v.z = ((he.z - hs.z) + (le.z - ls.z)) * inv;
            v.w = ((he.w - hs.w) + (le.w - ls.w)) * inv;
            __stcs((float4*)(ps + eg * LL), v);   // streaming store: write-once output
        }
    }
}

extern "C" void kernel_launch(void* const* d_in, const int* in_sizes, int n_in,
                              void* d_out, int out_size) {
    const float* apc   = (const float*)d_in[0];
    const float* aroot = (const float*)d_in[1];
    const float* aqual = (const float*)d_in[2];
    // d_in[3] = inactive_pc: unused by the reference
    const float* iroot = (const float*)d_in[4];
    const float* iqual = (const float*)d_in[5];
    const float* hpc   = (const float*)d_in[6];
    const float* hroot = (const float*)d_in[7];
    const float* hqual = (const float*)d_in[8];
    const int*   pco   = (n_in > 9) ? (const int*)d_in[9] : nullptr;

    static bool attr_done = false;
    if (!attr_done) {
        cudaFuncSetAttribute(main_kernel, cudaFuncAttributeMaxDynamicSharedMemorySize,
                             SM_FLOATS * 4);
        attr_done = true;
    }

    prep_kernel<<<KK * BB + BB, 256>>>(apc, aroot, aqual, iroot, iqual,
                                       hpc, hroot, hqual, pco);
    d_kernel<<<dim3(TT + 1, BB), 224>>>();
    main_kernel<<<dim3(32, 8, BB), 256, SM_FLOATS * 4>>>((float*)d_out);
}